// round 6
// baseline (speedup 1.0000x reference)
#include <cuda_runtime.h>
#include <cuda_bf16.h>

#define NB      65536
#define THREADS 192
#define SPB     32

// ---- shared memory layout (u32/f32 offsets) ----
#define OFF_WA   0        // [10][32] f32
#define OFF_WB   320      // [10][32] f32
#define OFF_W2   640      // [32][20] f32 rows (80B each, 16B aligned)
#define OFF_W3   1280     // [20]
#define OFF_SB2  1300     // [20]  (byte off 5200, 16B aligned)
#define OFF_CW1  1320     // [6][20]
#define OFF_CB1  1440     // [6][20]
#define OFF_CW2  1560     // [6][20][12]
#define OFF_CB2  3000     // [6][12]
#define OFF_OUTW 3072     // [80]
#define OFF_MISC 3152     // [0]=sb3,[1]=out_b
#define OFF_PETA 3156     // [192]
#define OFF_C1   3348     // [78][16] u32 (bf16x2)
#define OFF_AB   4596     // [32][388] u32; rows A0..A11,B0..B11 of 16 u32
#define AB_STRIDE 388
#define SMEM_U32 (OFF_AB + SPB * AB_STRIDE)

extern __shared__ float smem[];

__device__ __forceinline__ unsigned f2bf(float a, float b) {
    __nv_bfloat162 h = __floats2bfloat162_rn(a, b);
    return *reinterpret_cast<unsigned*>(&h);
}
__device__ __forceinline__ unsigned long long pack_dup(unsigned f) {
    unsigned long long r;
    asm("mov.b64 %0, {%1, %1};" : "=l"(r) : "r"(f));
    return r;
}
__device__ __forceinline__ void ffma2(unsigned long long& d,
                                      unsigned long long a, unsigned long long b) {
    asm("fma.rn.f32x2 %0, %1, %2, %3;" : "=l"(d) : "l"(a), "l"(b), "l"(d));
}
__device__ __forceinline__ void unpack2(unsigned long long v, float& lo, float& hi) {
    asm("mov.b64 {%0, %1}, %2;" : "=f"(lo), "=f"(hi) : "l"(v));
}

__global__ void __launch_bounds__(THREADS, 2)
pin_kernel(const float* __restrict__ x_cont, const int* __restrict__ x_cat,
           const float* __restrict__ exposure,
           const float* __restrict__ cont_W1, const float* __restrict__ cont_b1,
           const float* __restrict__ cont_W2, const float* __restrict__ cont_b2,
           const float* __restrict__ cat_tables, const float* __restrict__ tokens,
           const float* __restrict__ sW1, const float* __restrict__ sb1,
           const float* __restrict__ sW2, const float* __restrict__ sb2,
           const float* __restrict__ sW3, const float* __restrict__ sb3,
           const float* __restrict__ out_w, const float* __restrict__ out_b,
           float* __restrict__ out)
{
    unsigned* smemu = (unsigned*)smem;
    const int tid  = threadIdx.x;
    const int lane = tid & 31;
    const int sub  = tid >> 5;

    // ---------------- staging ----------------
    for (int i = tid; i < 320; i += THREADS) {
        int d = i >> 5, l = i & 31;
        smem[OFF_WA + i] = (l < 30) ? sW1[d * 30 + l] : 0.f;
        smem[OFF_WB + i] = (l < 30) ? sW1[(10 + d) * 30 + l] : 0.f;
    }
    for (int i = tid; i < 640; i += THREADS) {
        int l = i / 20, o = i % 20;
        smem[OFF_W2 + i] = (l < 30) ? sW2[l * 20 + o] : 0.f;
    }
    for (int i = tid; i < 20; i += THREADS) {
        smem[OFF_W3 + i]  = sW3[i];
        smem[OFF_SB2 + i] = sb2[i];
    }
    for (int i = tid; i < 120; i += THREADS) {
        smem[OFF_CW1 + i] = cont_W1[i];
        smem[OFF_CB1 + i] = cont_b1[i];
    }
    for (int i = tid; i < 1200; i += THREADS) {
        int c = i / 200, r = i % 200, h = r / 10, d = r % 10;
        smem[OFF_CW2 + (c * 20 + h) * 12 + d] = cont_W2[i];
    }
    for (int i = tid; i < 60; i += THREADS)
        smem[OFF_CB2 + (i / 10) * 12 + (i % 10)] = cont_b2[i];
    for (int i = tid; i < 78; i += THREADS) smem[OFF_OUTW + i] = out_w[i];
    if (tid == 0) { smem[OFF_MISC + 0] = sb3[0]; smem[OFF_MISC + 1] = out_b[0]; }
    for (int i = tid; i < 78 * 16; i += THREADS) {
        int p = i >> 4, lp = i & 15;
        int l0 = lp * 2, l1 = l0 + 1;
        float v0 = 0.f, v1 = 0.f;
        if (l0 < 30) {
            v0 = sb1[l0];
#pragma unroll
            for (int d = 0; d < 10; ++d)
                v0 = fmaf(tokens[p * 10 + d], sW1[(20 + d) * 30 + l0], v0);
        }
        if (l1 < 30) {
            v1 = sb1[l1];
#pragma unroll
            for (int d = 0; d < 10; ++d)
                v1 = fmaf(tokens[p * 10 + d], sW1[(20 + d) * 30 + l1], v1);
        }
        smemu[OFF_C1 + i] = f2bf(v0, v1);
    }
    __syncthreads();

    // ---------------- per-sample feature + projection ----------------
    const int b = blockIdx.x * SPB + lane;
    unsigned* myAB = smemu + OFF_AB + lane * AB_STRIDE;

    float e[10];
    {
        int c = sub;
        float x = x_cont[b * 6 + c];
#pragma unroll
        for (int d = 0; d < 10; ++d) e[d] = smem[OFF_CB2 + c * 12 + d];
#pragma unroll
        for (int h = 0; h < 20; ++h) {
            float hv = fmaxf(fmaf(x, smem[OFF_CW1 + c * 20 + h],
                                  smem[OFF_CB1 + c * 20 + h]), 0.f);
#pragma unroll
            for (int d = 0; d < 10; ++d)
                e[d] = fmaf(hv, smem[OFF_CW2 + (c * 20 + h) * 12 + d], e[d]);
        }
    }
#pragma unroll 1
    for (int proj = 0; proj < 2; ++proj) {
        const float* W = smem + (proj ? OFF_WB : OFF_WA);
        float acc[32];
#pragma unroll
        for (int l = 0; l < 32; ++l) acc[l] = 0.f;
#pragma unroll
        for (int d = 0; d < 10; ++d)
#pragma unroll
            for (int l = 0; l < 32; ++l)
                acc[l] = fmaf(e[d], W[d * 32 + l], acc[l]);
        unsigned* dst = myAB + (proj ? (12 + sub) : sub) * 16;
#pragma unroll
        for (int i = 0; i < 16; ++i) dst[i] = f2bf(acc[2 * i], acc[2 * i + 1]);
    }
    {
        int c = sub;
        int idx = x_cat[b * 6 + c];
        const float2* row = (const float2*)(cat_tables + (size_t)(c * 100 + idx) * 10);
#pragma unroll
        for (int d = 0; d < 5; ++d) { float2 v = row[d]; e[2*d] = v.x; e[2*d+1] = v.y; }
    }
#pragma unroll 1
    for (int proj = 0; proj < 2; ++proj) {
        const float* W = smem + (proj ? OFF_WB : OFF_WA);
        float acc[32];
#pragma unroll
        for (int l = 0; l < 32; ++l) acc[l] = 0.f;
#pragma unroll
        for (int d = 0; d < 10; ++d)
#pragma unroll
            for (int l = 0; l < 32; ++l)
                acc[l] = fmaf(e[d], W[d * 32 + l], acc[l]);
        unsigned* dst = myAB + (proj ? (18 + sub) : (6 + sub)) * 16;
#pragma unroll
        for (int i = 0; i < 16; ++i) dst[i] = f2bf(acc[2 * i], acc[2 * i + 1]);
    }
    __syncthreads();

    // ---------------- pair loop: rows {sub, 11-sub} = 13 pairs ----------------
    const float raw_bias = smem[OFF_MISC + 0];
    const __nv_bfloat162 z2 = __floats2bfloat162_rn(0.f, 0.f);
    float eta = 0.f;

#pragma unroll 1
    for (int r = 0; r < 2; ++r) {
        const int j = r ? (11 - sub) : sub;
        const int pbase = (j * (25 - j)) >> 1;
        const uint4* Aj = (const uint4*)(myAB + j * 16);

#pragma unroll 1
        for (int k = j; k < 12; ++k) {
            const int p = pbase + (k - j);
            const uint4* Bk = (const uint4*)(myAB + (12 + k) * 16);
            const uint4* Cp = (const uint4*)(smemu + OFF_C1 + p * 16);

            unsigned long long h2[10];
            {
                const ulonglong2* sbp = (const ulonglong2*)(smem + OFF_SB2);
                ulonglong2 s0 = sbp[0], s1 = sbp[1], s2 = sbp[2], s3 = sbp[3], s4 = sbp[4];
                h2[0]=s0.x; h2[1]=s0.y; h2[2]=s1.x; h2[3]=s1.y; h2[4]=s2.x;
                h2[5]=s2.y; h2[6]=s3.x; h2[7]=s3.y; h2[8]=s4.x; h2[9]=s4.y;
            }

#pragma unroll
            for (int g = 0; g < 4; ++g) {
                uint4 ag = Aj[g], bg = Bk[g], cg = Cp[g];
#pragma unroll
                for (int i = 0; i < 4; ++i) {
                    if (g * 4 + i < 15) {
                        unsigned ua = (i==0)?ag.x:(i==1)?ag.y:(i==2)?ag.z:ag.w;
                        unsigned ub = (i==0)?bg.x:(i==1)?bg.y:(i==2)?bg.z:bg.w;
                        unsigned uc = (i==0)?cg.x:(i==1)?cg.y:(i==2)?cg.z:cg.w;
                        __nv_bfloat162 ta = *reinterpret_cast<__nv_bfloat162*>(&ua);
                        __nv_bfloat162 tb = *reinterpret_cast<__nv_bfloat162*>(&ub);
                        __nv_bfloat162 tc = *reinterpret_cast<__nv_bfloat162*>(&uc);
                        __nv_bfloat162 t = __hmax2(__hadd2(__hadd2(ta, tb), tc), z2);
                        unsigned u = *reinterpret_cast<unsigned*>(&t);
                        unsigned long long hl = pack_dup(u << 16);
                        unsigned long long hh = pack_dup(u & 0xFFFF0000u);

                        const int l0 = (g * 4 + i) * 2;
                        {
                            const ulonglong2* w0 =
                                (const ulonglong2*)(smem + OFF_W2 + l0 * 20);
                            ulonglong2 p0=w0[0], p1=w0[1], p2=w0[2], p3=w0[3], p4=w0[4];
                            ffma2(h2[0], hl, p0.x); ffma2(h2[1], hl, p0.y);
                            ffma2(h2[2], hl, p1.x); ffma2(h2[3], hl, p1.y);
                            ffma2(h2[4], hl, p2.x); ffma2(h2[5], hl, p2.y);
                            ffma2(h2[6], hl, p3.x); ffma2(h2[7], hl, p3.y);
                            ffma2(h2[8], hl, p4.x); ffma2(h2[9], hl, p4.y);
                        }
                        {
                            const ulonglong2* w1 =
                                (const ulonglong2*)(smem + OFF_W2 + (l0 + 1) * 20);
                            ulonglong2 p0=w1[0], p1=w1[1], p2=w1[2], p3=w1[3], p4=w1[4];
                            ffma2(h2[0], hh, p0.x); ffma2(h2[1], hh, p0.y);
                            ffma2(h2[2], hh, p1.x); ffma2(h2[3], hh, p1.y);
                            ffma2(h2[4], hh, p2.x); ffma2(h2[5], hh, p2.y);
                            ffma2(h2[6], hh, p3.x); ffma2(h2[7], hh, p3.y);
                            ffma2(h2[8], hh, p4.x); ffma2(h2[9], hh, p4.y);
                        }
                    }
                }
            }

            float raw = raw_bias;
            {
                const float4* w3r = (const float4*)(smem + OFF_W3);
#pragma unroll
                for (int v = 0; v < 5; ++v) {
                    float4 w = w3r[v];
                    float lo, hi;
                    unpack2(h2[2 * v], lo, hi);
                    raw = fmaf(fmaxf(lo, 0.f), w.x, raw);
                    raw = fmaf(fmaxf(hi, 0.f), w.y, raw);
                    unpack2(h2[2 * v + 1], lo, hi);
                    raw = fmaf(fmaxf(lo, 0.f), w.z, raw);
                    raw = fmaf(fmaxf(hi, 0.f), w.w, raw);
                }
            }
            float ht = fminf(fmaxf(raw * (1.f/6.f) + 0.5f, 0.f), 1.f) - 0.5f;
            eta = fmaf(smem[OFF_OUTW + p], ht, eta);
        }
    }

    smem[OFF_PETA + tid] = eta;
    __syncthreads();
    if (tid < 32) {
        float esum = 0.f;
#pragma unroll
        for (int s = 0; s < 6; ++s) esum += smem[OFF_PETA + tid + 32 * s];
        esum += smem[OFF_MISC + 1];
        esum = fminf(fmaxf(esum, -20.f), 20.f);
        out[b] = __expf(esum) * exposure[b];
    }
}

extern "C" void kernel_launch(void* const* d_in, const int* in_sizes, int n_in,
                              void* d_out, int out_size)
{
    (void)in_sizes; (void)n_in; (void)out_size;
    size_t shmem = SMEM_U32 * 4;
    cudaFuncSetAttribute(pin_kernel, cudaFuncAttributeMaxDynamicSharedMemorySize,
                         (int)shmem);
    pin_kernel<<<NB / SPB, THREADS, shmem>>>(
        (const float*)d_in[0],  (const int*)d_in[1],   (const float*)d_in[2],
        (const float*)d_in[3],  (const float*)d_in[4], (const float*)d_in[5],
        (const float*)d_in[6],  (const float*)d_in[7], (const float*)d_in[8],
        (const float*)d_in[9],  (const float*)d_in[10],(const float*)d_in[11],
        (const float*)d_in[12], (const float*)d_in[13],(const float*)d_in[14],
        (const float*)d_in[15], (const float*)d_in[16],
        (float*)d_out);
}

// round 7
// speedup vs baseline: 3.9658x; 3.9658x over previous
#include <cuda_runtime.h>
#include <cuda_bf16.h>

#define NB      65536
#define THREADS 192
#define SPB     32

// ---- shared memory layout (u32/f32 offsets) ----
#define OFF_WA    0       // [10][32] f32
#define OFF_WB    320     // [10][32] f32
#define OFF_W2B   640     // [30][12] u32 bf16x2 (outputs packed 2/u32, 2 pad)
#define OFF_SB2B  1000    // [12] u32 bf16x2
#define OFF_W3    1012    // [20] f32
#define OFF_CW1   1032    // [6][20]
#define OFF_CB1   1152    // [6][20]
#define OFF_CW2   1272    // [6][20][12]
#define OFF_CB2   2712    // [6][12]
#define OFF_OUTW  2784    // [80]
#define OFF_MISC  2864    // [0]=sb3,[1]=out_b
#define OFF_PETA  2866    // [192]
#define OFF_C1    3060    // [78][16] u32 bf16x2   (16B aligned)
#define OFF_AB    4308    // [32][388] u32; rows A0..A11,B0..B11 of 16 u32
#define AB_STRIDE 388
#define SMEM_U32  (OFF_AB + SPB * AB_STRIDE)   // 16724 u32 = 66896 B

extern __shared__ float smem[];

__device__ __forceinline__ unsigned f2bf(float a, float b) {
    __nv_bfloat162 h = __floats2bfloat162_rn(a, b);
    return *reinterpret_cast<unsigned*>(&h);
}
__device__ __forceinline__ __nv_bfloat162 uib(unsigned u) {
    return *reinterpret_cast<__nv_bfloat162*>(&u);
}
__device__ __forceinline__ unsigned biu(__nv_bfloat162 h) {
    return *reinterpret_cast<unsigned*>(&h);
}
__device__ __forceinline__ unsigned dup_lo(unsigned u) {
    unsigned r; asm("prmt.b32 %0, %1, %1, 0x1010;" : "=r"(r) : "r"(u)); return r;
}
__device__ __forceinline__ unsigned dup_hi(unsigned u) {
    unsigned r; asm("prmt.b32 %0, %1, %1, 0x3232;" : "=r"(r) : "r"(u)); return r;
}

__global__ void __launch_bounds__(THREADS, 2)
pin_kernel(const float* __restrict__ x_cont, const int* __restrict__ x_cat,
           const float* __restrict__ exposure,
           const float* __restrict__ cont_W1, const float* __restrict__ cont_b1,
           const float* __restrict__ cont_W2, const float* __restrict__ cont_b2,
           const float* __restrict__ cat_tables, const float* __restrict__ tokens,
           const float* __restrict__ sW1, const float* __restrict__ sb1,
           const float* __restrict__ sW2, const float* __restrict__ sb2,
           const float* __restrict__ sW3, const float* __restrict__ sb3,
           const float* __restrict__ out_w, const float* __restrict__ out_b,
           float* __restrict__ out)
{
    unsigned* smemu = (unsigned*)smem;
    const int tid  = threadIdx.x;
    const int lane = tid & 31;
    const int sub  = tid >> 5;

    // ---------------- staging ----------------
    for (int i = tid; i < 320; i += THREADS) {
        int d = i >> 5, l = i & 31;
        smem[OFF_WA + i] = (l < 30) ? sW1[d * 30 + l] : 0.f;
        smem[OFF_WB + i] = (l < 30) ? sW1[(10 + d) * 30 + l] : 0.f;
    }
    for (int i = tid; i < 360; i += THREADS) {      // W2 bf16x2 rows
        int l = i / 12, up = i % 12;
        float v0 = (up < 10) ? sW2[l * 20 + up * 2]     : 0.f;
        float v1 = (up < 10) ? sW2[l * 20 + up * 2 + 1] : 0.f;
        smemu[OFF_W2B + i] = f2bf(v0, v1);
    }
    for (int i = tid; i < 12; i += THREADS) {
        float v0 = (i < 10) ? sb2[i * 2]     : 0.f;
        float v1 = (i < 10) ? sb2[i * 2 + 1] : 0.f;
        smemu[OFF_SB2B + i] = f2bf(v0, v1);
    }
    for (int i = tid; i < 20; i += THREADS) smem[OFF_W3 + i] = sW3[i];
    for (int i = tid; i < 120; i += THREADS) {
        smem[OFF_CW1 + i] = cont_W1[i];
        smem[OFF_CB1 + i] = cont_b1[i];
    }
    for (int i = tid; i < 1200; i += THREADS) {
        int c = i / 200, r = i % 200, h = r / 10, d = r % 10;
        smem[OFF_CW2 + (c * 20 + h) * 12 + d] = cont_W2[i];
    }
    for (int i = tid; i < 60; i += THREADS)
        smem[OFF_CB2 + (i / 10) * 12 + (i % 10)] = cont_b2[i];
    for (int i = tid; i < 78; i += THREADS) smem[OFF_OUTW + i] = out_w[i];
    if (tid == 0) { smem[OFF_MISC + 0] = sb3[0]; smem[OFF_MISC + 1] = out_b[0]; }
    for (int i = tid; i < 78 * 16; i += THREADS) {
        int p = i >> 4, lp = i & 15;
        int l0 = lp * 2, l1 = l0 + 1;
        float v0 = 0.f, v1 = 0.f;
        if (l0 < 30) {
            v0 = sb1[l0];
#pragma unroll
            for (int d = 0; d < 10; ++d)
                v0 = fmaf(tokens[p * 10 + d], sW1[(20 + d) * 30 + l0], v0);
        }
        if (l1 < 30) {
            v1 = sb1[l1];
#pragma unroll
            for (int d = 0; d < 10; ++d)
                v1 = fmaf(tokens[p * 10 + d], sW1[(20 + d) * 30 + l1], v1);
        }
        smemu[OFF_C1 + i] = f2bf(v0, v1);
    }
    __syncthreads();

    // ---------------- per-sample feature + projection (f32) ----------------
    const int b = blockIdx.x * SPB + lane;
    unsigned* myAB = smemu + OFF_AB + lane * AB_STRIDE;

    float e[10];
    {
        int c = sub;
        float x = x_cont[b * 6 + c];
#pragma unroll
        for (int d = 0; d < 10; ++d) e[d] = smem[OFF_CB2 + c * 12 + d];
#pragma unroll
        for (int h = 0; h < 20; ++h) {
            float hv = fmaxf(fmaf(x, smem[OFF_CW1 + c * 20 + h],
                                  smem[OFF_CB1 + c * 20 + h]), 0.f);
#pragma unroll
            for (int d = 0; d < 10; ++d)
                e[d] = fmaf(hv, smem[OFF_CW2 + (c * 20 + h) * 12 + d], e[d]);
        }
    }
#pragma unroll 1
    for (int proj = 0; proj < 2; ++proj) {
        const float* W = smem + (proj ? OFF_WB : OFF_WA);
        float acc[32];
#pragma unroll
        for (int l = 0; l < 32; ++l) acc[l] = 0.f;
#pragma unroll
        for (int d = 0; d < 10; ++d)
#pragma unroll
            for (int l = 0; l < 32; ++l)
                acc[l] = fmaf(e[d], W[d * 32 + l], acc[l]);
        unsigned* dst = myAB + (proj ? (12 + sub) : sub) * 16;
#pragma unroll
        for (int i = 0; i < 16; ++i) dst[i] = f2bf(acc[2 * i], acc[2 * i + 1]);
    }
    {
        int c = sub;
        int idx = x_cat[b * 6 + c];
        const float2* row = (const float2*)(cat_tables + (size_t)(c * 100 + idx) * 10);
#pragma unroll
        for (int d = 0; d < 5; ++d) { float2 v = row[d]; e[2*d] = v.x; e[2*d+1] = v.y; }
    }
#pragma unroll 1
    for (int proj = 0; proj < 2; ++proj) {
        const float* W = smem + (proj ? OFF_WB : OFF_WA);
        float acc[32];
#pragma unroll
        for (int l = 0; l < 32; ++l) acc[l] = 0.f;
#pragma unroll
        for (int d = 0; d < 10; ++d)
#pragma unroll
            for (int l = 0; l < 32; ++l)
                acc[l] = fmaf(e[d], W[d * 32 + l], acc[l]);
        unsigned* dst = myAB + (proj ? (18 + sub) : (6 + sub)) * 16;
#pragma unroll
        for (int i = 0; i < 16; ++i) dst[i] = f2bf(acc[2 * i], acc[2 * i + 1]);
    }
    __syncthreads();

    // ---------------- pair loop: rows {sub, 11-sub} = 13 pairs ----------------
    const float raw_bias = smem[OFF_MISC + 0];
    const __nv_bfloat162 z2 = __floats2bfloat162_rn(0.f, 0.f);
    float eta = 0.f;

#define H1STEP(idx, ua, ub, uc)                                         \
    h1u[idx] = biu(__hmax2(__hadd2(__hadd2(uib(ua), uib(ub)), uib(uc)), z2))

#pragma unroll 1
    for (int r = 0; r < 2; ++r) {
        const int j = r ? (11 - sub) : sub;
        const int pbase = (j * (25 - j)) >> 1;
        const uint4* Aj = (const uint4*)(myAB + j * 16);

#pragma unroll 1
        for (int k = j; k < 12; ++k) {
            const int p = pbase + (k - j);
            const uint4* Bk = (const uint4*)(myAB + (12 + k) * 16);
            const uint4* Cp = (const uint4*)(smemu + OFF_C1 + p * 16);

            // ---- h1 (30 vals as 15 bf16x2) ----
            unsigned h1u[15];
            {
                uint4 a = Aj[0], bb = Bk[0], c = Cp[0];
                H1STEP(0, a.x, bb.x, c.x); H1STEP(1, a.y, bb.y, c.y);
                H1STEP(2, a.z, bb.z, c.z); H1STEP(3, a.w, bb.w, c.w);
            }
            {
                uint4 a = Aj[1], bb = Bk[1], c = Cp[1];
                H1STEP(4, a.x, bb.x, c.x); H1STEP(5, a.y, bb.y, c.y);
                H1STEP(6, a.z, bb.z, c.z); H1STEP(7, a.w, bb.w, c.w);
            }
            {
                uint4 a = Aj[2], bb = Bk[2], c = Cp[2];
                H1STEP(8, a.x, bb.x, c.x); H1STEP(9, a.y, bb.y, c.y);
                H1STEP(10, a.z, bb.z, c.z); H1STEP(11, a.w, bb.w, c.w);
            }
            {
                uint4 a = Aj[3], bb = Bk[3], c = Cp[3];
                H1STEP(12, a.x, bb.x, c.x); H1STEP(13, a.y, bb.y, c.y);
                H1STEP(14, a.z, bb.z, c.z);
            }

            // ---- h2 accumulate (bf16x2, 10 accumulators) ----
            __nv_bfloat162 h2v[10];
            {
                const uint4* sbp = (const uint4*)(smemu + OFF_SB2B);
                uint4 s0 = sbp[0], s1 = sbp[1], s2 = sbp[2];
                h2v[0]=uib(s0.x); h2v[1]=uib(s0.y); h2v[2]=uib(s0.z); h2v[3]=uib(s0.w);
                h2v[4]=uib(s1.x); h2v[5]=uib(s1.y); h2v[6]=uib(s1.z); h2v[7]=uib(s1.w);
                h2v[8]=uib(s2.x); h2v[9]=uib(s2.y);
            }

#pragma unroll
            for (int lp = 0; lp < 15; ++lp) {
                unsigned u = h1u[lp];
                __nv_bfloat162 lo2 = uib(dup_lo(u));
                __nv_bfloat162 hi2 = uib(dup_hi(u));
                const uint4* wr = (const uint4*)(smemu + OFF_W2B + lp * 24);
                uint4 r0 = wr[0], r1 = wr[1], r2 = wr[2];   // row 2*lp
                uint4 q0 = wr[3], q1 = wr[4], q2 = wr[5];   // row 2*lp+1
                h2v[0] = __hfma2(lo2, uib(r0.x), h2v[0]);
                h2v[1] = __hfma2(lo2, uib(r0.y), h2v[1]);
                h2v[2] = __hfma2(lo2, uib(r0.z), h2v[2]);
                h2v[3] = __hfma2(lo2, uib(r0.w), h2v[3]);
                h2v[4] = __hfma2(lo2, uib(r1.x), h2v[4]);
                h2v[5] = __hfma2(lo2, uib(r1.y), h2v[5]);
                h2v[6] = __hfma2(lo2, uib(r1.z), h2v[6]);
                h2v[7] = __hfma2(lo2, uib(r1.w), h2v[7]);
                h2v[8] = __hfma2(lo2, uib(r2.x), h2v[8]);
                h2v[9] = __hfma2(lo2, uib(r2.y), h2v[9]);
                h2v[0] = __hfma2(hi2, uib(q0.x), h2v[0]);
                h2v[1] = __hfma2(hi2, uib(q0.y), h2v[1]);
                h2v[2] = __hfma2(hi2, uib(q0.z), h2v[2]);
                h2v[3] = __hfma2(hi2, uib(q0.w), h2v[3]);
                h2v[4] = __hfma2(hi2, uib(q1.x), h2v[4]);
                h2v[5] = __hfma2(hi2, uib(q1.y), h2v[5]);
                h2v[6] = __hfma2(hi2, uib(q1.z), h2v[6]);
                h2v[7] = __hfma2(hi2, uib(q1.w), h2v[7]);
                h2v[8] = __hfma2(hi2, uib(q2.x), h2v[8]);
                h2v[9] = __hfma2(hi2, uib(q2.y), h2v[9]);
            }

            // ---- tail (f32) ----
            float raw = raw_bias;
            {
                const float4* w3r = (const float4*)(smem + OFF_W3);
#pragma unroll
                for (int v = 0; v < 5; ++v) {
                    float4 w = w3r[v];
                    float2 f0 = __bfloat1622float2(__hmax2(h2v[2 * v], z2));
                    float2 f1 = __bfloat1622float2(__hmax2(h2v[2 * v + 1], z2));
                    raw = fmaf(f0.x, w.x, raw);
                    raw = fmaf(f0.y, w.y, raw);
                    raw = fmaf(f1.x, w.z, raw);
                    raw = fmaf(f1.y, w.w, raw);
                }
            }
            float ht = fminf(fmaxf(raw * (1.f/6.f) + 0.5f, 0.f), 1.f) - 0.5f;
            eta = fmaf(smem[OFF_OUTW + p], ht, eta);
        }
    }

    smem[OFF_PETA + tid] = eta;
    __syncthreads();
    if (tid < 32) {
        float esum = 0.f;
#pragma unroll
        for (int s = 0; s < 6; ++s) esum += smem[OFF_PETA + tid + 32 * s];
        esum += smem[OFF_MISC + 1];
        esum = fminf(fmaxf(esum, -20.f), 20.f);
        out[b] = __expf(esum) * exposure[b];
    }
}

extern "C" void kernel_launch(void* const* d_in, const int* in_sizes, int n_in,
                              void* d_out, int out_size)
{
    (void)in_sizes; (void)n_in; (void)out_size;
    size_t shmem = SMEM_U32 * 4;
    cudaFuncSetAttribute(pin_kernel, cudaFuncAttributeMaxDynamicSharedMemorySize,
                         (int)shmem);
    pin_kernel<<<NB / SPB, THREADS, shmem>>>(
        (const float*)d_in[0],  (const int*)d_in[1],   (const float*)d_in[2],
        (const float*)d_in[3],  (const float*)d_in[4], (const float*)d_in[5],
        (const float*)d_in[6],  (const float*)d_in[7], (const float*)d_in[8],
        (const float*)d_in[9],  (const float*)d_in[10],(const float*)d_in[11],
        (const float*)d_in[12], (const float*)d_in[13],(const float*)d_in[14],
        (const float*)d_in[15], (const float*)d_in[16],
        (float*)d_out);
}